// round 10
// baseline (speedup 1.0000x reference)
#include <cuda_runtime.h>

// 2-layer GCN: R8 aggregation/prescale + K-paired f32x2 GEMMs (MOV-free, narrow col tiles).

#define N_NODES 50000
#define DIM_IN 64
#define DIM_HID 128
#define CAP 128

typedef unsigned long long u64;

__device__ __forceinline__ void fma2(u64& d, u64 a, u64 b) {
    asm("fma.rn.f32x2 %0, %1, %2, %3;" : "=l"(d) : "l"(a), "l"(b), "l"(d));
}
__device__ __forceinline__ float2 up(u64 v) {
    float2 f; asm("mov.b64 {%0, %1}, %2;" : "=f"(f.x), "=f"(f.y) : "l"(v)); return f;
}

__device__ int   g_cnt[N_NODES];
__device__ int   g_bucket[N_NODES * CAP];
__device__ float g_dinv[N_NODES];
__device__ float g_y   [N_NODES * DIM_IN];
__device__ float g_z   [N_NODES * DIM_IN];
__device__ float g_h   [N_NODES * DIM_HID];
__device__ float g_y2  [N_NODES * DIM_IN];

// ---------------- build ----------------
__global__ void k_place(const int* __restrict__ src, const int* __restrict__ dst, int e) {
    int i = blockIdx.x * blockDim.x + threadIdx.x;
    if (i < e) {
        int d = dst[i];
        int pos = atomicAdd(&g_cnt[d], 1);
        g_bucket[d * CAP + pos] = src[i];
    }
}

// ---------------- prescale: y = dinv*x ; materialize dinv (R8) ----------------
__global__ void k_prescale(const float* __restrict__ x, float* __restrict__ y, int n) {
    int idx = blockIdx.x * blockDim.x + threadIdx.x;  // n*16
    if (idx >= n * 16) return;
    int i = idx >> 4;
    float d = rsqrtf((float)g_cnt[i] + 1.0f);
    if ((idx & 15) == 0) g_dinv[i] = d;
    float4 v = reinterpret_cast<const float4*>(x)[idx];
    float4 o = {d * v.x, d * v.y, d * v.z, d * v.w};
    reinterpret_cast<float4*>(y)[idx] = o;
}

// ---------------- gather aggregation (R5/R8, measured 25.0us) ----------------
template <bool FINISH>
__global__ void k_agg(const float* __restrict__ F, float* __restrict__ O,
                      const float* __restrict__ bias, int n) {
    int node = blockIdx.x * 32 + threadIdx.y;
    if (node >= n) return;
    int lane = threadIdx.x;
    const float4* F4 = reinterpret_cast<const float4*>(F);
    const int4* cols4 = reinterpret_cast<const int4*>(g_bucket + node * CAP);
    int cnt = g_cnt[node];

    float4 acc = F4[node * 16 + lane];  // self term
    int j = 0;
    for (; j + 4 <= cnt; j += 4) {
        int4 c = __ldg(&cols4[j >> 2]);
        float4 u0 = F4[c.x * 16 + lane];
        float4 u1 = F4[c.y * 16 + lane];
        float4 u2 = F4[c.z * 16 + lane];
        float4 u3 = F4[c.w * 16 + lane];
        acc.x += (u0.x + u1.x) + (u2.x + u3.x);
        acc.y += (u0.y + u1.y) + (u2.y + u3.y);
        acc.z += (u0.z + u1.z) + (u2.z + u3.z);
        acc.w += (u0.w + u1.w) + (u2.w + u3.w);
    }
    if (j < cnt) {
        int4 c = __ldg(&cols4[j >> 2]);
        int rem = cnt - j;
        float4 u0 = F4[c.x * 16 + lane];
        acc.x += u0.x; acc.y += u0.y; acc.z += u0.z; acc.w += u0.w;
        if (rem > 1) {
            float4 u1 = F4[c.y * 16 + lane];
            acc.x += u1.x; acc.y += u1.y; acc.z += u1.z; acc.w += u1.w;
        }
        if (rem > 2) {
            float4 u2 = F4[c.z * 16 + lane];
            acc.x += u2.x; acc.y += u2.y; acc.z += u2.z; acc.w += u2.w;
        }
    }
    float4 o;
    if (FINISH) {
        float di = g_dinv[node];
        float4 bb = reinterpret_cast<const float4*>(bias)[lane];
        o.x = fmaf(di, acc.x, bb.x);
        o.y = fmaf(di, acc.y, bb.y);
        o.z = fmaf(di, acc.z, bb.z);
        o.w = fmaf(di, acc.w, bb.w);
    } else {
        o = acc;
    }
    reinterpret_cast<float4*>(O)[node * 16 + lane] = o;
}

// ---------------- GEMM1: h = relu(b1 + dinv[r]*(z@W1))  [n,64]x[64,128] ----------------
// block (64,4): tx -> cols {tx, tx+64}; 8 rows/thread => 32 rows/block.
// Wt[j][k] smem (stride 68), K-paired f32x2, A loaded directly as ull2 (no pack MOVs).
#define W1_STRIDE 68
__global__ void __launch_bounds__(256) k_gemm1(
        const float* __restrict__ Z, const float* __restrict__ W,
        const float* __restrict__ b, float* __restrict__ H, int n) {
    __shared__ float Ws[128 * W1_STRIDE];
    int tid = threadIdx.y * 64 + threadIdx.x;
    for (int i = tid; i < 64 * 128; i += 256) {
        int k = i >> 7, j = i & 127;        // W[k][j], row-major [64,128]
        Ws[j * W1_STRIDE + k] = W[i];
    }
    __syncthreads();
    int tx = threadIdx.x;
    int r0 = blockIdx.x * 32 + threadIdx.y * 8;
    int rr[8];
    #pragma unroll
    for (int q = 0; q < 8; q++) rr[q] = min(r0 + q, n - 1);
    const ulonglong2* A2 = reinterpret_cast<const ulonglong2*>(Z);  // row = 16 x ull2
    u64 acc[8][2] = {};
    #pragma unroll
    for (int k4 = 0; k4 < 16; k4++) {
        ulonglong2 a[8];
        #pragma unroll
        for (int q = 0; q < 8; q++) a[q] = A2[rr[q] * 16 + k4];
        #pragma unroll
        for (int c = 0; c < 2; c++) {
            int col = c * 64 + tx;
            ulonglong2 w = *reinterpret_cast<const ulonglong2*>(&Ws[col * W1_STRIDE + k4 * 4]);
            #pragma unroll
            for (int q = 0; q < 8; q++) {
                fma2(acc[q][c], a[q].x, w.x);
                fma2(acc[q][c], a[q].y, w.y);
            }
        }
    }
    float bb0 = b[tx], bb1 = b[64 + tx];
    #pragma unroll
    for (int q = 0; q < 8; q++) {
        int r = r0 + q;
        if (r < n) {
            float s = g_dinv[r];
            float2 f0 = up(acc[q][0]);
            float2 f1 = up(acc[q][1]);
            H[(size_t)r * 128 + tx]      = fmaxf(fmaf(s, f0.x + f0.y, bb0), 0.f);
            H[(size_t)r * 128 + 64 + tx] = fmaxf(fmaf(s, f1.x + f1.y, bb1), 0.f);
        }
    }
}

// ---------------- GEMM2: y2 = dinv[r]*(h@W2)  [n,128]x[128,64] ----------------
// block (64,4): tx -> 1 col; 8 rows/thread => 32 rows/block. Wt stride 132.
#define W2_STRIDE 132
__global__ void __launch_bounds__(256) k_gemm2(
        const float* __restrict__ H, const float* __restrict__ W,
        float* __restrict__ Y2, int n) {
    __shared__ float Ws[64 * W2_STRIDE];
    int tid = threadIdx.y * 64 + threadIdx.x;
    for (int i = tid; i < 128 * 64; i += 256) {
        int k = i >> 6, j = i & 63;         // W[k][j], row-major [128,64]
        Ws[j * W2_STRIDE + k] = W[i];
    }
    __syncthreads();
    int tx = threadIdx.x;
    int r0 = blockIdx.x * 32 + threadIdx.y * 8;
    int rr[8];
    #pragma unroll
    for (int q = 0; q < 8; q++) rr[q] = min(r0 + q, n - 1);
    const ulonglong2* A2 = reinterpret_cast<const ulonglong2*>(H);  // row = 32 x ull2
    u64 acc[8] = {};
    #pragma unroll
    for (int k4 = 0; k4 < 32; k4++) {
        ulonglong2 a[8];
        #pragma unroll
        for (int q = 0; q < 8; q++) a[q] = A2[rr[q] * 32 + k4];
        ulonglong2 w = *reinterpret_cast<const ulonglong2*>(&Ws[tx * W2_STRIDE + k4 * 4]);
        #pragma unroll
        for (int q = 0; q < 8; q++) {
            fma2(acc[q], a[q].x, w.x);
            fma2(acc[q], a[q].y, w.y);
        }
    }
    #pragma unroll
    for (int q = 0; q < 8; q++) {
        int r = r0 + q;
        if (r < n) {
            float s = g_dinv[r];
            float2 f = up(acc[q]);
            Y2[(size_t)r * 64 + tx] = s * (f.x + f.y);
        }
    }
}

extern "C" void kernel_launch(void* const* d_in, const int* in_sizes, int n_in,
                              void* d_out, int out_size) {
    const float* x  = (const float*)d_in[0];
    const int*   ei = (const int*)  d_in[1];
    const float* W1 = (const float*)d_in[2];
    const float* b1 = (const float*)d_in[3];
    const float* W2 = (const float*)d_in[4];
    const float* b2 = (const float*)d_in[5];
    float* out = (float*)d_out;

    int n = in_sizes[0] / DIM_IN;   // 50000
    int e = in_sizes[1] / 2;        // 800000
    const int* src = ei;
    const int* dst = ei + e;

    float *y, *z, *h, *y2;
    int* cnt;
    cudaGetSymbolAddress((void**)&y,   g_y);
    cudaGetSymbolAddress((void**)&z,   g_z);
    cudaGetSymbolAddress((void**)&h,   g_h);
    cudaGetSymbolAddress((void**)&y2,  g_y2);
    cudaGetSymbolAddress((void**)&cnt, g_cnt);

    const int TB = 256;

    // build
    cudaMemsetAsync(cnt, 0, (size_t)n * sizeof(int));
    k_place<<<(e + TB - 1) / TB, TB>>>(src, dst, e);

    // layer 1
    k_prescale<<<(n * 16 + TB - 1) / TB, TB>>>(x, y, n);
    k_agg<false><<<(n + 31) / 32, dim3(16, 32)>>>(y, z, nullptr, n);
    k_gemm1<<<(n + 31) / 32, dim3(64, 4)>>>(z, W1, b1, h, n);

    // layer 2
    k_gemm2<<<(n + 31) / 32, dim3(64, 4)>>>(h, W2, y2, n);
    k_agg<true><<<(n + 31) / 32, dim3(16, 32)>>>(y2, out, b2, n);
}

// round 11
// speedup vs baseline: 1.3260x; 1.3260x over previous
#include <cuda_runtime.h>

// 2-layer GCN: R8 gather aggregation + 3xTF32 tensor-core GEMMs (mma.sync m16n8k8).

#define N_NODES 50000
#define DIM_IN 64
#define DIM_HID 128
#define CAP 128

__device__ int   g_cnt[N_NODES];
__device__ int   g_bucket[N_NODES * CAP];
__device__ float g_dinv[N_NODES];
__device__ float g_y   [N_NODES * DIM_IN];
__device__ float g_z   [N_NODES * DIM_IN];
__device__ float g_h   [N_NODES * DIM_HID];
__device__ float g_y2  [N_NODES * DIM_IN];

// Precomputed B fragments (lane-ordered) for W1 / W2, hi+lo tf32 split.
// W1: 8 ktiles x 16 coltiles x 32 lanes;  W2: 16 ktiles x 8 coltiles x 32 lanes.
__device__ float2 g_w1hi[8 * 16 * 32];
__device__ float2 g_w1lo[8 * 16 * 32];
__device__ float2 g_w2hi[16 * 8 * 32];
__device__ float2 g_w2lo[16 * 8 * 32];

__device__ __forceinline__ unsigned to_tf32(float f) {
    unsigned r; asm("cvt.rna.tf32.f32 %0, %1;" : "=r"(r) : "f"(f)); return r;
}
__device__ __forceinline__ void split_tf32(float v, unsigned& hi, unsigned& lo) {
    hi = to_tf32(v);
    lo = to_tf32(v - __uint_as_float(hi));
}
__device__ __forceinline__ void mma_tf32(float* d, const unsigned* a, unsigned b0, unsigned b1) {
    asm volatile(
        "mma.sync.aligned.m16n8k8.row.col.f32.tf32.tf32.f32 "
        "{%0,%1,%2,%3}, {%4,%5,%6,%7}, {%8,%9}, {%0,%1,%2,%3};"
        : "+f"(d[0]), "+f"(d[1]), "+f"(d[2]), "+f"(d[3])
        : "r"(a[0]), "r"(a[1]), "r"(a[2]), "r"(a[3]), "r"(b0), "r"(b1));
}

// ---------------- build ----------------
__global__ void k_place(const int* __restrict__ src, const int* __restrict__ dst, int e) {
    int i = blockIdx.x * blockDim.x + threadIdx.x;
    if (i < e) {
        int d = dst[i];
        int pos = atomicAdd(&g_cnt[d], 1);
        g_bucket[d * CAP + pos] = src[i];
    }
}

// ---------------- W fragment precompute ----------------
// B-frag layout for mma row.col: b0 = B[k0+tig][n0+gid], b1 = B[k0+tig+4][n0+gid].
__global__ void k_wfrag1(const float* __restrict__ W) {   // W1 [64,128]
    int i = blockIdx.x * blockDim.x + threadIdx.x;        // 8*16*32 = 4096
    if (i >= 8 * 16 * 32) return;
    int kc = i >> 9, rest = i & 511, ct = rest >> 5, lane = rest & 31;
    int tig = lane & 3, gid = lane >> 2;
    int k = kc * 8 + tig, nn = ct * 8 + gid;
    float v0 = W[k * 128 + nn];
    float v1 = W[(k + 4) * 128 + nn];
    unsigned h0, l0, h1, l1;
    split_tf32(v0, h0, l0);
    split_tf32(v1, h1, l1);
    g_w1hi[i] = make_float2(__uint_as_float(h0), __uint_as_float(h1));
    g_w1lo[i] = make_float2(__uint_as_float(l0), __uint_as_float(l1));
}
__global__ void k_wfrag2(const float* __restrict__ W) {   // W2 [128,64]
    int i = blockIdx.x * blockDim.x + threadIdx.x;        // 16*8*32 = 4096
    if (i >= 16 * 8 * 32) return;
    int kc = i >> 8, rest = i & 255, ct = rest >> 5, lane = rest & 31;
    int tig = lane & 3, gid = lane >> 2;
    int k = kc * 8 + tig, nn = ct * 8 + gid;
    float v0 = W[k * 64 + nn];
    float v1 = W[(k + 4) * 64 + nn];
    unsigned h0, l0, h1, l1;
    split_tf32(v0, h0, l0);
    split_tf32(v1, h1, l1);
    g_w2hi[i] = make_float2(__uint_as_float(h0), __uint_as_float(h1));
    g_w2lo[i] = make_float2(__uint_as_float(l0), __uint_as_float(l1));
}

// ---------------- prescale: y = dinv*x ; materialize dinv (R8) ----------------
__global__ void k_prescale(const float* __restrict__ x, float* __restrict__ y, int n) {
    int idx = blockIdx.x * blockDim.x + threadIdx.x;  // n*16
    if (idx >= n * 16) return;
    int i = idx >> 4;
    float d = rsqrtf((float)g_cnt[i] + 1.0f);
    if ((idx & 15) == 0) g_dinv[i] = d;
    float4 v = reinterpret_cast<const float4*>(x)[idx];
    float4 o = {d * v.x, d * v.y, d * v.z, d * v.w};
    reinterpret_cast<float4*>(y)[idx] = o;
}

// ---------------- gather aggregation (R5/R8, measured 25.0us) ----------------
template <bool FINISH>
__global__ void k_agg(const float* __restrict__ F, float* __restrict__ O,
                      const float* __restrict__ bias, int n) {
    int node = blockIdx.x * 32 + threadIdx.y;
    if (node >= n) return;
    int lane = threadIdx.x;
    const float4* F4 = reinterpret_cast<const float4*>(F);
    const int4* cols4 = reinterpret_cast<const int4*>(g_bucket + node * CAP);
    int cnt = g_cnt[node];

    float4 acc = F4[node * 16 + lane];  // self term
    int j = 0;
    for (; j + 4 <= cnt; j += 4) {
        int4 c = __ldg(&cols4[j >> 2]);
        float4 u0 = F4[c.x * 16 + lane];
        float4 u1 = F4[c.y * 16 + lane];
        float4 u2 = F4[c.z * 16 + lane];
        float4 u3 = F4[c.w * 16 + lane];
        acc.x += (u0.x + u1.x) + (u2.x + u3.x);
        acc.y += (u0.y + u1.y) + (u2.y + u3.y);
        acc.z += (u0.z + u1.z) + (u2.z + u3.z);
        acc.w += (u0.w + u1.w) + (u2.w + u3.w);
    }
    if (j < cnt) {
        int4 c = __ldg(&cols4[j >> 2]);
        int rem = cnt - j;
        float4 u0 = F4[c.x * 16 + lane];
        acc.x += u0.x; acc.y += u0.y; acc.z += u0.z; acc.w += u0.w;
        if (rem > 1) {
            float4 u1 = F4[c.y * 16 + lane];
            acc.x += u1.x; acc.y += u1.y; acc.z += u1.z; acc.w += u1.w;
        }
        if (rem > 2) {
            float4 u2 = F4[c.z * 16 + lane];
            acc.x += u2.x; acc.y += u2.y; acc.z += u2.z; acc.w += u2.w;
        }
    }
    float4 o;
    if (FINISH) {
        float di = g_dinv[node];
        float4 bb = reinterpret_cast<const float4*>(bias)[lane];
        o.x = fmaf(di, acc.x, bb.x);
        o.y = fmaf(di, acc.y, bb.y);
        o.z = fmaf(di, acc.z, bb.z);
        o.w = fmaf(di, acc.w, bb.w);
    } else {
        o = acc;
    }
    reinterpret_cast<float4*>(O)[node * 16 + lane] = o;
}

// ---------------- GEMM1 (tensor): h = relu(b1 + dinv[r]*(z@W1))  [n,64]x[64,128] ----------------
// 8 warps/block, warp = 16 rows x 128 cols. 3xTF32. No smem.
__global__ void __launch_bounds__(256) k_gemm1(
        const float* __restrict__ Z, const float* __restrict__ b,
        float* __restrict__ H, int n) {
    int warp = threadIdx.x >> 5, lane = threadIdx.x & 31;
    int gid = lane >> 2, tig = lane & 3;
    int r0 = blockIdx.x * 128 + warp * 16;
    if (r0 >= n) return;                    // n % 16 == 0 -> warps never split
    int rowA = (r0 + gid) * 64;
    int rowB = (r0 + gid + 8) * 64;

    float acc[16][4];
    #pragma unroll
    for (int ct = 0; ct < 16; ct++)
        #pragma unroll
        for (int q = 0; q < 4; q++) acc[ct][q] = 0.f;

    for (int kc = 0; kc < 8; kc++) {
        int k0 = kc * 8 + tig;
        float a0 = __ldg(&Z[rowA + k0]);
        float a1 = __ldg(&Z[rowB + k0]);
        float a2 = __ldg(&Z[rowA + k0 + 4]);
        float a3 = __ldg(&Z[rowB + k0 + 4]);
        unsigned ah[4], al[4];
        split_tf32(a0, ah[0], al[0]);
        split_tf32(a1, ah[1], al[1]);
        split_tf32(a2, ah[2], al[2]);
        split_tf32(a3, ah[3], al[3]);
        int base = kc * 16 * 32 + lane;
        #pragma unroll
        for (int ct = 0; ct < 16; ct++) {
            float2 h2 = g_w1hi[base + ct * 32];
            float2 l2 = g_w1lo[base + ct * 32];
            unsigned bh0 = __float_as_uint(h2.x), bh1 = __float_as_uint(h2.y);
            unsigned bl0 = __float_as_uint(l2.x), bl1 = __float_as_uint(l2.y);
            mma_tf32(acc[ct], ah, bh0, bh1);
            mma_tf32(acc[ct], ah, bl0, bl1);
            mma_tf32(acc[ct], al, bh0, bh1);
        }
    }
    float s0 = g_dinv[r0 + gid];
    float s1 = g_dinv[r0 + gid + 8];
    #pragma unroll
    for (int ct = 0; ct < 16; ct++) {
        int nc = ct * 8 + 2 * tig;
        float bb0 = b[nc], bb1 = b[nc + 1];
        H[(size_t)(r0 + gid) * 128 + nc]         = fmaxf(fmaf(s0, acc[ct][0], bb0), 0.f);
        H[(size_t)(r0 + gid) * 128 + nc + 1]     = fmaxf(fmaf(s0, acc[ct][1], bb1), 0.f);
        H[(size_t)(r0 + gid + 8) * 128 + nc]     = fmaxf(fmaf(s1, acc[ct][2], bb0), 0.f);
        H[(size_t)(r0 + gid + 8) * 128 + nc + 1] = fmaxf(fmaf(s1, acc[ct][3], bb1), 0.f);
    }
}

// ---------------- GEMM2 (tensor): y2 = dinv[r]*(h@W2)  [n,128]x[128,64] ----------------
__global__ void __launch_bounds__(256) k_gemm2(
        const float* __restrict__ Hm, float* __restrict__ Y2, int n) {
    int warp = threadIdx.x >> 5, lane = threadIdx.x & 31;
    int gid = lane >> 2, tig = lane & 3;
    int r0 = blockIdx.x * 128 + warp * 16;
    if (r0 >= n) return;
    int rowA = (r0 + gid) * 128;
    int rowB = (r0 + gid + 8) * 128;

    float acc[8][4];
    #pragma unroll
    for (int ct = 0; ct < 8; ct++)
        #pragma unroll
        for (int q = 0; q < 4; q++) acc[ct][q] = 0.f;

    for (int kc = 0; kc < 16; kc++) {
        int k0 = kc * 8 + tig;
        float a0 = __ldg(&Hm[rowA + k0]);
        float a1 = __ldg(&Hm[rowB + k0]);
        float a2 = __ldg(&Hm[rowA + k0 + 4]);
        float a3 = __ldg(&Hm[rowB + k0 + 4]);
        unsigned ah[4], al[4];
        split_tf32(a0, ah[0], al[0]);
        split_tf32(a1, ah[1], al[1]);
        split_tf32(a2, ah[2], al[2]);
        split_tf32(a3, ah[3], al[3]);
        int base = kc * 8 * 32 + lane;
        #pragma unroll
        for (int ct = 0; ct < 8; ct++) {
            float2 h2 = g_w2hi[base + ct * 32];
            float2 l2 = g_w2lo[base + ct * 32];
            unsigned bh0 = __float_as_uint(h2.x), bh1 = __float_as_uint(h2.y);
            unsigned bl0 = __float_as_uint(l2.x), bl1 = __float_as_uint(l2.y);
            mma_tf32(acc[ct], ah, bh0, bh1);
            mma_tf32(acc[ct], ah, bl0, bl1);
            mma_tf32(acc[ct], al, bh0, bh1);
        }
    }
    float s0 = g_dinv[r0 + gid];
    float s1 = g_dinv[r0 + gid + 8];
    #pragma unroll
    for (int ct = 0; ct < 8; ct++) {
        int nc = ct * 8 + 2 * tig;
        Y2[(size_t)(r0 + gid) * 64 + nc]         = s0 * acc[ct][0];
        Y2[(size_t)(r0 + gid) * 64 + nc + 1]     = s0 * acc[ct][1];
        Y2[(size_t)(r0 + gid + 8) * 64 + nc]     = s1 * acc[ct][2];
        Y2[(size_t)(r0 + gid + 8) * 64 + nc + 1] = s1 * acc[ct][3];
    }
}

extern "C" void kernel_launch(void* const* d_in, const int* in_sizes, int n_in,
                              void* d_out, int out_size) {
    const float* x  = (const float*)d_in[0];
    const int*   ei = (const int*)  d_in[1];
    const float* W1 = (const float*)d_in[2];
    const float* b1 = (const float*)d_in[3];
    const float* W2 = (const float*)d_in[4];
    const float* b2 = (const float*)d_in[5];
    float* out = (float*)d_out;

    int n = in_sizes[0] / DIM_IN;   // 50000
    int e = in_sizes[1] / 2;        // 800000
    const int* src = ei;
    const int* dst = ei + e;

    float *y, *z, *h, *y2;
    int* cnt;
    cudaGetSymbolAddress((void**)&y,   g_y);
    cudaGetSymbolAddress((void**)&z,   g_z);
    cudaGetSymbolAddress((void**)&h,   g_h);
    cudaGetSymbolAddress((void**)&y2,  g_y2);
    cudaGetSymbolAddress((void**)&cnt, g_cnt);

    const int TB = 256;

    // build + W fragment tables
    cudaMemsetAsync(cnt, 0, (size_t)n * sizeof(int));
    k_place <<<(e + TB - 1) / TB, TB>>>(src, dst, e);
    k_wfrag1<<<16, 256>>>(W1);
    k_wfrag2<<<16, 256>>>(W2);

    // layer 1
    k_prescale<<<(n * 16 + TB - 1) / TB, TB>>>(x, y, n);
    k_agg<false><<<(n + 31) / 32, dim3(16, 32)>>>(y, z, nullptr, n);
    k_gemm1<<<(n + 127) / 128, 256>>>(z, b1, h, n);

    // layer 2
    k_gemm2<<<(n + 127) / 128, 256>>>(h, y2, n);
    k_agg<true><<<(n + 31) / 32, dim3(16, 32)>>>(y2, out, b2, n);
}

// round 12
// speedup vs baseline: 1.3659x; 1.0301x over previous
#include <cuda_runtime.h>

// 2-layer GCN: R8 structure + occupancy-tuned launch bounds.

#define N_NODES 50000
#define DIM_IN 64
#define DIM_HID 128
#define CAP 128

typedef unsigned long long u64;

__device__ __forceinline__ u64 pk(float v) {
    u64 r; asm("mov.b64 %0, {%1, %1};" : "=l"(r) : "f"(v)); return r;
}
__device__ __forceinline__ void fma2(u64& d, u64 a, u64 b) {
    asm("fma.rn.f32x2 %0, %1, %2, %3;" : "=l"(d) : "l"(a), "l"(b), "l"(d));
}
__device__ __forceinline__ float2 up(u64 v) {
    float2 f; asm("mov.b64 {%0, %1}, %2;" : "=f"(f.x), "=f"(f.y) : "l"(v)); return f;
}

__device__ int   g_cnt[N_NODES];
__device__ int   g_bucket[N_NODES * CAP];
__device__ float g_dinv[N_NODES];
__device__ float g_y   [N_NODES * DIM_IN];
__device__ float g_z   [N_NODES * DIM_IN];
__device__ float g_h   [N_NODES * DIM_HID];
__device__ float g_y2  [N_NODES * DIM_IN];

// ---------------- build ----------------
__global__ void k_place(const int* __restrict__ src, const int* __restrict__ dst, int e) {
    int i = blockIdx.x * blockDim.x + threadIdx.x;
    if (i < e) {
        int d = dst[i];
        int pos = atomicAdd(&g_cnt[d], 1);
        g_bucket[d * CAP + pos] = src[i];
    }
}

// ---------------- prescale: y = dinv*x ; materialize dinv ----------------
__global__ void k_prescale(const float* __restrict__ x, float* __restrict__ y, int n) {
    int idx = blockIdx.x * blockDim.x + threadIdx.x;  // n*16
    if (idx >= n * 16) return;
    int i = idx >> 4;
    float d = rsqrtf((float)g_cnt[i] + 1.0f);
    if ((idx & 15) == 0) g_dinv[i] = d;
    float4 v = reinterpret_cast<const float4*>(x)[idx];
    float4 o = {d * v.x, d * v.y, d * v.z, d * v.w};
    reinterpret_cast<float4*>(y)[idx] = o;
}

// ---------------- gather aggregation (R5 core, occupancy-pinned) ----------------
template <bool FINISH>
__global__ void __launch_bounds__(512, 3) k_agg(
        const float* __restrict__ F, float* __restrict__ O,
        const float* __restrict__ bias, int n) {
    int node = blockIdx.x * 32 + threadIdx.y;
    if (node >= n) return;
    int lane = threadIdx.x;
    const float4* F4 = reinterpret_cast<const float4*>(F);
    const int4* cols4 = reinterpret_cast<const int4*>(g_bucket + node * CAP);
    int cnt = g_cnt[node];

    float4 acc = F4[node * 16 + lane];  // self term
    int j = 0;
    for (; j + 4 <= cnt; j += 4) {
        int4 c = __ldg(&cols4[j >> 2]);
        float4 u0 = F4[c.x * 16 + lane];
        float4 u1 = F4[c.y * 16 + lane];
        float4 u2 = F4[c.z * 16 + lane];
        float4 u3 = F4[c.w * 16 + lane];
        acc.x += (u0.x + u1.x) + (u2.x + u3.x);
        acc.y += (u0.y + u1.y) + (u2.y + u3.y);
        acc.z += (u0.z + u1.z) + (u2.z + u3.z);
        acc.w += (u0.w + u1.w) + (u2.w + u3.w);
    }
    if (j < cnt) {
        int4 c = __ldg(&cols4[j >> 2]);
        int rem = cnt - j;
        float4 u0 = F4[c.x * 16 + lane];
        acc.x += u0.x; acc.y += u0.y; acc.z += u0.z; acc.w += u0.w;
        if (rem > 1) {
            float4 u1 = F4[c.y * 16 + lane];
            acc.x += u1.x; acc.y += u1.y; acc.z += u1.z; acc.w += u1.w;
        }
        if (rem > 2) {
            float4 u2 = F4[c.z * 16 + lane];
            acc.x += u2.x; acc.y += u2.y; acc.z += u2.z; acc.w += u2.w;
        }
    }
    float4 o;
    if (FINISH) {
        float di = g_dinv[node];
        float4 bb = reinterpret_cast<const float4*>(bias)[lane];
        o.x = fmaf(di, acc.x, bb.x);
        o.y = fmaf(di, acc.y, bb.y);
        o.z = fmaf(di, acc.z, bb.z);
        o.w = fmaf(di, acc.w, bb.w);
    } else {
        o = acc;
    }
    reinterpret_cast<float4*>(O)[node * 16 + lane] = o;
}

// ---------------- GEMM1: h = relu(b1 + dinv[r]*(z@W1))  [n,64]x[64,128] ----------------
// block (32,8), 8 rows/thread => 64 rows/block. f32x2 FMA, reg-capped for 3 blocks/SM.
__global__ void __launch_bounds__(256, 3) k_gemm1(
        const float* __restrict__ Z, const float* __restrict__ W,
        const float* __restrict__ b, float* __restrict__ H, int n) {
    __shared__ float Ws[64 * 128];
    int tid = threadIdx.y * 32 + threadIdx.x;
    {
        const float4* w4 = reinterpret_cast<const float4*>(W);
        float4* s4 = reinterpret_cast<float4*>(Ws);
        for (int i = tid; i < 64 * 128 / 4; i += 256) s4[i] = w4[i];
    }
    __syncthreads();
    int tx = threadIdx.x;
    int r0 = blockIdx.x * 64 + threadIdx.y * 8;
    int rr[8];
    #pragma unroll
    for (int q = 0; q < 8; q++) rr[q] = min(r0 + q, n - 1);
    const float4* A4 = reinterpret_cast<const float4*>(Z);
    const ulonglong2* ws2 = reinterpret_cast<const ulonglong2*>(Ws);
    u64 acc[8][2] = {};
    #pragma unroll
    for (int k4 = 0; k4 < 16; k4++) {
        float va[8][4];
        #pragma unroll
        for (int q = 0; q < 8; q++) {
            float4 v = A4[rr[q] * 16 + k4];
            va[q][0] = v.x; va[q][1] = v.y; va[q][2] = v.z; va[q][3] = v.w;
        }
        #pragma unroll
        for (int s = 0; s < 4; s++) {
            ulonglong2 w = ws2[(4 * k4 + s) * 32 + tx];
            #pragma unroll
            for (int q = 0; q < 8; q++) {
                u64 m = pk(va[q][s]);
                fma2(acc[q][0], m, w.x);
                fma2(acc[q][1], m, w.y);
            }
        }
    }
    float4 bb = reinterpret_cast<const float4*>(b)[tx];
    float4* H4 = reinterpret_cast<float4*>(H);
    #pragma unroll
    for (int q = 0; q < 8; q++) {
        int r = r0 + q;
        if (r < n) {
            float s = g_dinv[r];
            float2 lo = up(acc[q][0]);
            float2 hi = up(acc[q][1]);
            float4 o;
            o.x = fmaxf(fmaf(s, lo.x, bb.x), 0.f);
            o.y = fmaxf(fmaf(s, lo.y, bb.y), 0.f);
            o.z = fmaxf(fmaf(s, hi.x, bb.z), 0.f);
            o.w = fmaxf(fmaf(s, hi.y, bb.w), 0.f);
            H4[(size_t)r * 32 + tx] = o;
        }
    }
}

// ---------------- GEMM2: y2 = dinv[r]*(h@W2)  [n,128]x[128,64] ----------------
// block (16,16), 8 rows/thread => 128 rows/block.
__global__ void __launch_bounds__(256, 3) k_gemm2(
        const float* __restrict__ H, const float* __restrict__ W,
        float* __restrict__ Y2, int n) {
    __shared__ float Ws[128 * 64];
    int tid = threadIdx.y * 16 + threadIdx.x;
    {
        const float4* w4 = reinterpret_cast<const float4*>(W);
        float4* s4 = reinterpret_cast<float4*>(Ws);
        for (int i = tid; i < 128 * 64 / 4; i += 256) s4[i] = w4[i];
    }
    __syncthreads();
    int tx = threadIdx.x;
    int r0 = blockIdx.x * 128 + threadIdx.y * 8;
    int rr[8];
    #pragma unroll
    for (int q = 0; q < 8; q++) rr[q] = min(r0 + q, n - 1);
    const float4* A4 = reinterpret_cast<const float4*>(H);
    const ulonglong2* ws2 = reinterpret_cast<const ulonglong2*>(Ws);
    u64 acc[8][2] = {};
    #pragma unroll
    for (int k4 = 0; k4 < 32; k4++) {
        float va[8][4];
        #pragma unroll
        for (int q = 0; q < 8; q++) {
            float4 v = A4[rr[q] * 32 + k4];
            va[q][0] = v.x; va[q][1] = v.y; va[q][2] = v.z; va[q][3] = v.w;
        }
        #pragma unroll
        for (int s = 0; s < 4; s++) {
            ulonglong2 w = ws2[(4 * k4 + s) * 16 + tx];
            #pragma unroll
            for (int q = 0; q < 8; q++) {
                u64 m = pk(va[q][s]);
                fma2(acc[q][0], m, w.x);
                fma2(acc[q][1], m, w.y);
            }
        }
    }
    float4* Y4 = reinterpret_cast<float4*>(Y2);
    #pragma unroll
    for (int q = 0; q < 8; q++) {
        int r = r0 + q;
        if (r < n) {
            float s = g_dinv[r];
            float2 lo = up(acc[q][0]);
            float2 hi = up(acc[q][1]);
            float4 o = {s * lo.x, s * lo.y, s * hi.x, s * hi.y};
            Y4[(size_t)r * 16 + tx] = o;
        }
    }
}

extern "C" void kernel_launch(void* const* d_in, const int* in_sizes, int n_in,
                              void* d_out, int out_size) {
    const float* x  = (const float*)d_in[0];
    const int*   ei = (const int*)  d_in[1];
    const float* W1 = (const float*)d_in[2];
    const float* b1 = (const float*)d_in[3];
    const float* W2 = (const float*)d_in[4];
    const float* b2 = (const float*)d_in[5];
    float* out = (float*)d_out;

    int n = in_sizes[0] / DIM_IN;   // 50000
    int e = in_sizes[1] / 2;        // 800000
    const int* src = ei;
    const int* dst = ei + e;

    float *y, *z, *h, *y2;
    int* cnt;
    cudaGetSymbolAddress((void**)&y,   g_y);
    cudaGetSymbolAddress((void**)&z,   g_z);
    cudaGetSymbolAddress((void**)&h,   g_h);
    cudaGetSymbolAddress((void**)&y2,  g_y2);
    cudaGetSymbolAddress((void**)&cnt, g_cnt);

    const int TB = 256;

    // build
    cudaMemsetAsync(cnt, 0, (size_t)n * sizeof(int));
    k_place<<<(e + TB - 1) / TB, TB>>>(src, dst, e);

    // layer 1
    k_prescale<<<(n * 16 + TB - 1) / TB, TB>>>(x, y, n);
    k_agg<false><<<(n + 31) / 32, dim3(16, 32)>>>(y, z, nullptr, n);
    k_gemm1<<<(n + 63) / 64, dim3(32, 8)>>>(z, W1, b1, h, n);

    // layer 2
    k_gemm2<<<(n + 127) / 128, dim3(16, 16)>>>(h, W2, y2, n);
    k_agg<true><<<(n + 31) / 32, dim3(16, 32)>>>(y2, out, b2, n);
}

// round 13
// speedup vs baseline: 1.4676x; 1.0744x over previous
#include <cuda_runtime.h>

// 2-layer GCN: R8 structure; only change = launch_bounds(512,3) on k_agg.

#define N_NODES 50000
#define DIM_IN 64
#define DIM_HID 128
#define CAP 128

typedef unsigned long long u64;

__device__ __forceinline__ u64 pk(float v) {
    u64 r; asm("mov.b64 %0, {%1, %1};" : "=l"(r) : "f"(v)); return r;
}
__device__ __forceinline__ void fma2(u64& d, u64 a, u64 b) {
    asm("fma.rn.f32x2 %0, %1, %2, %3;" : "=l"(d) : "l"(a), "l"(b), "l"(d));
}
__device__ __forceinline__ float2 up(u64 v) {
    float2 f; asm("mov.b64 {%0, %1}, %2;" : "=f"(f.x), "=f"(f.y) : "l"(v)); return f;
}

__device__ int   g_cnt[N_NODES];
__device__ int   g_bucket[N_NODES * CAP];
__device__ float g_dinv[N_NODES];
__device__ float g_y   [N_NODES * DIM_IN];
__device__ float g_z   [N_NODES * DIM_IN];
__device__ float g_h   [N_NODES * DIM_HID];
__device__ float g_y2  [N_NODES * DIM_IN];

// ---------------- build ----------------
__global__ void k_place(const int* __restrict__ src, const int* __restrict__ dst, int e) {
    int i = blockIdx.x * blockDim.x + threadIdx.x;
    if (i < e) {
        int d = dst[i];
        int pos = atomicAdd(&g_cnt[d], 1);
        g_bucket[d * CAP + pos] = src[i];
    }
}

// ---------------- prescale: y = dinv*x ; materialize dinv ----------------
__global__ void k_prescale(const float* __restrict__ x, float* __restrict__ y, int n) {
    int idx = blockIdx.x * blockDim.x + threadIdx.x;  // n*16
    if (idx >= n * 16) return;
    int i = idx >> 4;
    float d = rsqrtf((float)g_cnt[i] + 1.0f);
    if ((idx & 15) == 0) g_dinv[i] = d;
    float4 v = reinterpret_cast<const float4*>(x)[idx];
    float4 o = {d * v.x, d * v.y, d * v.z, d * v.w};
    reinterpret_cast<float4*>(y)[idx] = o;
}

// ---------------- gather aggregation (R5 core, occ-pinned; 38 regs fits 42 cap) --------
template <bool FINISH>
__global__ void __launch_bounds__(512, 3) k_agg(
        const float* __restrict__ F, float* __restrict__ O,
        const float* __restrict__ bias, int n) {
    int node = blockIdx.x * 32 + threadIdx.y;
    if (node >= n) return;
    int lane = threadIdx.x;
    const float4* F4 = reinterpret_cast<const float4*>(F);
    const int4* cols4 = reinterpret_cast<const int4*>(g_bucket + node * CAP);
    int cnt = g_cnt[node];

    float4 acc = F4[node * 16 + lane];  // self term
    int j = 0;
    for (; j + 4 <= cnt; j += 4) {
        int4 c = __ldg(&cols4[j >> 2]);
        float4 u0 = F4[c.x * 16 + lane];
        float4 u1 = F4[c.y * 16 + lane];
        float4 u2 = F4[c.z * 16 + lane];
        float4 u3 = F4[c.w * 16 + lane];
        acc.x += (u0.x + u1.x) + (u2.x + u3.x);
        acc.y += (u0.y + u1.y) + (u2.y + u3.y);
        acc.z += (u0.z + u1.z) + (u2.z + u3.z);
        acc.w += (u0.w + u1.w) + (u2.w + u3.w);
    }
    if (j < cnt) {
        int4 c = __ldg(&cols4[j >> 2]);
        int rem = cnt - j;
        float4 u0 = F4[c.x * 16 + lane];
        acc.x += u0.x; acc.y += u0.y; acc.z += u0.z; acc.w += u0.w;
        if (rem > 1) {
            float4 u1 = F4[c.y * 16 + lane];
            acc.x += u1.x; acc.y += u1.y; acc.z += u1.z; acc.w += u1.w;
        }
        if (rem > 2) {
            float4 u2 = F4[c.z * 16 + lane];
            acc.x += u2.x; acc.y += u2.y; acc.z += u2.z; acc.w += u2.w;
        }
    }
    float4 o;
    if (FINISH) {
        float di = g_dinv[node];
        float4 bb = reinterpret_cast<const float4*>(bias)[lane];
        o.x = fmaf(di, acc.x, bb.x);
        o.y = fmaf(di, acc.y, bb.y);
        o.z = fmaf(di, acc.z, bb.z);
        o.w = fmaf(di, acc.w, bb.w);
    } else {
        o = acc;
    }
    reinterpret_cast<float4*>(O)[node * 16 + lane] = o;
}

// ---------------- GEMM1: h = relu(b1 + dinv[r]*(z@W1))  [n,64]x[64,128] ----------------
// block (32,8), 8 rows/thread => 64 rows/block. Unconstrained regs (R8-measured best).
__global__ void __launch_bounds__(256) k_gemm1(
        const float* __restrict__ Z, const float* __restrict__ W,
        const float* __restrict__ b, float* __restrict__ H, int n) {
    __shared__ float Ws[64 * 128];
    int tid = threadIdx.y * 32 + threadIdx.x;
    {
        const float4* w4 = reinterpret_cast<const float4*>(W);
        float4* s4 = reinterpret_cast<float4*>(Ws);
        for (int i = tid; i < 64 * 128 / 4; i += 256) s4[i] = w4[i];
    }
    __syncthreads();
    int tx = threadIdx.x;
    int r0 = blockIdx.x * 64 + threadIdx.y * 8;
    int rr[8];
    #pragma unroll
    for (int q = 0; q < 8; q++) rr[q] = min(r0 + q, n - 1);
    const float4* A4 = reinterpret_cast<const float4*>(Z);
    const ulonglong2* ws2 = reinterpret_cast<const ulonglong2*>(Ws);
    u64 acc[8][2] = {};
    #pragma unroll
    for (int k4 = 0; k4 < 16; k4++) {
        float va[8][4];
        #pragma unroll
        for (int q = 0; q < 8; q++) {
            float4 v = A4[rr[q] * 16 + k4];
            va[q][0] = v.x; va[q][1] = v.y; va[q][2] = v.z; va[q][3] = v.w;
        }
        #pragma unroll
        for (int s = 0; s < 4; s++) {
            ulonglong2 w = ws2[(4 * k4 + s) * 32 + tx];
            #pragma unroll
            for (int q = 0; q < 8; q++) {
                u64 m = pk(va[q][s]);
                fma2(acc[q][0], m, w.x);
                fma2(acc[q][1], m, w.y);
            }
        }
    }
    float4 bb = reinterpret_cast<const float4*>(b)[tx];
    float4* H4 = reinterpret_cast<float4*>(H);
    #pragma unroll
    for (int q = 0; q < 8; q++) {
        int r = r0 + q;
        if (r < n) {
            float s = g_dinv[r];
            float2 lo = up(acc[q][0]);
            float2 hi = up(acc[q][1]);
            float4 o;
            o.x = fmaxf(fmaf(s, lo.x, bb.x), 0.f);
            o.y = fmaxf(fmaf(s, lo.y, bb.y), 0.f);
            o.z = fmaxf(fmaf(s, hi.x, bb.z), 0.f);
            o.w = fmaxf(fmaf(s, hi.y, bb.w), 0.f);
            H4[(size_t)r * 32 + tx] = o;
        }
    }
}

// ---------------- GEMM2: y2 = dinv[r]*(h@W2)  [n,128]x[128,64] ----------------
// block (16,16), 8 rows/thread => 128 rows/block.
__global__ void __launch_bounds__(256) k_gemm2(
        const float* __restrict__ H, const float* __restrict__ W,
        float* __restrict__ Y2, int n) {
    __shared__ float Ws[128 * 64];
    int tid = threadIdx.y * 16 + threadIdx.x;
    {
        const float4* w4 = reinterpret_cast<const float4*>(W);
        float4* s4 = reinterpret_cast<float4*>(Ws);
        for (int i = tid; i < 128 * 64 / 4; i += 256) s4[i] = w4[i];
    }
    __syncthreads();
    int tx = threadIdx.x;
    int r0 = blockIdx.x * 128 + threadIdx.y * 8;
    int rr[8];
    #pragma unroll
    for (int q = 0; q < 8; q++) rr[q] = min(r0 + q, n - 1);
    const float4* A4 = reinterpret_cast<const float4*>(H);
    const ulonglong2* ws2 = reinterpret_cast<const ulonglong2*>(Ws);
    u64 acc[8][2] = {};
    #pragma unroll
    for (int k4 = 0; k4 < 32; k4++) {
        float va[8][4];
        #pragma unroll
        for (int q = 0; q < 8; q++) {
            float4 v = A4[rr[q] * 32 + k4];
            va[q][0] = v.x; va[q][1] = v.y; va[q][2] = v.z; va[q][3] = v.w;
        }
        #pragma unroll
        for (int s = 0; s < 4; s++) {
            ulonglong2 w = ws2[(4 * k4 + s) * 16 + tx];
            #pragma unroll
            for (int q = 0; q < 8; q++) {
                u64 m = pk(va[q][s]);
                fma2(acc[q][0], m, w.x);
                fma2(acc[q][1], m, w.y);
            }
        }
    }
    float4* Y4 = reinterpret_cast<float4*>(Y2);
    #pragma unroll
    for (int q = 0; q < 8; q++) {
        int r = r0 + q;
        if (r < n) {
            float s = g_dinv[r];
            float2 lo = up(acc[q][0]);
            float2 hi = up(acc[q][1]);
            float4 o = {s * lo.x, s * lo.y, s * hi.x, s * hi.y};
            Y4[(size_t)r * 16 + tx] = o;
        }
    }
}

extern "C" void kernel_launch(void* const* d_in, const int* in_sizes, int n_in,
                              void* d_out, int out_size) {
    const float* x  = (const float*)d_in[0];
    const int*   ei = (const int*)  d_in[1];
    const float* W1 = (const float*)d_in[2];
    const float* b1 = (const float*)d_in[3];
    const float* W2 = (const float*)d_in[4];
    const float* b2 = (const float*)d_in[5];
    float* out = (float*)d_out;

    int n = in_sizes[0] / DIM_IN;   // 50000
    int e = in_sizes[1] / 2;        // 800000
    const int* src = ei;
    const int* dst = ei + e;

    float *y, *z, *h, *y2;
    int* cnt;
    cudaGetSymbolAddress((void**)&y,   g_y);
    cudaGetSymbolAddress((void**)&z,   g_z);
    cudaGetSymbolAddress((void**)&h,   g_h);
    cudaGetSymbolAddress((void**)&y2,  g_y2);
    cudaGetSymbolAddress((void**)&cnt, g_cnt);

    const int TB = 256;

    // build
    cudaMemsetAsync(cnt, 0, (size_t)n * sizeof(int));
    k_place<<<(e + TB - 1) / TB, TB>>>(src, dst, e);

    // layer 1
    k_prescale<<<(n * 16 + TB - 1) / TB, TB>>>(x, y, n);
    k_agg<false><<<(n + 31) / 32, dim3(16, 32)>>>(y, z, nullptr, n);
    k_gemm1<<<(n + 63) / 64, dim3(32, 8)>>>(z, W1, b1, h, n);

    // layer 2
    k_gemm2<<<(n + 127) / 128, dim3(16, 16)>>>(h, W2, y2, n);
    k_agg<true><<<(n + 31) / 32, dim3(16, 32)>>>(y2, out, b2, n);
}